// round 1
// baseline (speedup 1.0000x reference)
#include <cuda_runtime.h>

// ============================================================================
// Sparse e3nn tensor product, uvu mode.
// irreps1 = 128x0e+128x1o+128x2e (x1: [Z,1152], per-l blocks are u-major)
// irreps2 = 1x0e+1x1o+1x2e      (x2: [Z,9])
// out     = irreps1 layout
//
// 11 instructions; real Wigner-3j values are computed EXACTLY on device
// (port of the reference su2_cg + real-basis transform, fp64) by a tiny init
// kernel each launch. Only the *sparsity pattern* (83 entries) is hardcoded,
// derived from the real-SH selection rules; entries that happen to be zero
// just get coefficient 0.0.
// ============================================================================

#define NE 83
#define NT 11

__device__ float cg_coef[NE];   // alpha-folded coefficients, written by init kernel

// per-instruction (l1,l2,l3)
__constant__ int TL1[NT] = {0,0,0,1,1,1,1,2,2,2,2};
__constant__ int TL2[NT] = {0,1,2,0,1,1,2,0,1,2,2};
__constant__ int TL3[NT] = {0,1,2,1,0,2,1,2,1,0,2};
// alpha = sqrt(dim_out / n_paths_to(io)); io per t = {0,1,2,1,0,2,1,2,1,0,2}
// io=0: sqrt(1/3), io=1: sqrt(3/4), io=2: sqrt(5/4)
__constant__ double TALPHA[NT] = {
  0.5773502691896258, 0.8660254037844386, 1.1180339887498949,
  0.8660254037844386, 0.5773502691896258, 1.1180339887498949,
  0.8660254037844386, 1.1180339887498949, 0.8660254037844386,
  0.5773502691896258, 1.1180339887498949};

// entry tables: instruction id and LOCAL (i,j,k) indices within each 3j tensor
__constant__ unsigned char ENT_T[NE] = {
  0,
  1,1,1,
  2,2,2,2,2,
  3,3,3,
  4,4,4,
  5,5,5,5,5,5,5,5,5,5,5,
  6,6,6,6,6,6,6,6,6,6,6,
  7,7,7,7,7,
  8,8,8,8,8,8,8,8,8,8,8,
  9,9,9,9,9,
  10,10,10,10,10,10,10,10,10,10,10,10,10,10,10,10,10,10,10,10,10,10,10,10,10};
__constant__ unsigned char ENT_I[NE] = {
  0,
  0,0,0,
  0,0,0,0,0,
  0,1,2,
  0,1,2,
  1,1,1,2,0,2,0,2,0,2,0,
  1,1,1,2,0,2,0,2,0,2,0,
  0,1,2,3,4,
  2,2,2,3,1,3,1,4,4,0,0,
  0,1,2,3,4,
  2,2,2,3,1,2,2,4,0,3,1,3,1,3,1,3,1,3,1,4,0,4,0,4,0};
__constant__ unsigned char ENT_J[NE] = {
  0,
  0,1,2,
  0,1,2,3,4,
  0,0,0,
  0,1,2,
  1,2,0,1,1,2,0,2,0,0,2,
  2,3,1,2,2,3,1,4,4,0,0,
  0,0,0,0,0,
  1,2,0,1,1,2,0,2,0,2,0,
  0,1,2,3,4,
  2,3,1,2,2,4,0,2,2,3,1,3,1,1,3,4,4,0,0,3,3,1,1,4,0};
__constant__ unsigned char ENT_K[NE] = {
  0,
  0,1,2,
  0,1,2,3,4,
  0,1,2,
  0,0,0,
  2,3,1,3,1,2,2,4,4,0,0,
  1,2,0,2,0,1,1,2,0,0,2,
  0,1,2,3,4,
  1,2,0,2,0,1,1,2,0,0,2,
  0,0,0,0,0,
  2,3,1,3,1,4,0,4,0,2,2,4,4,0,0,3,1,1,3,3,1,1,3,2,2};

// ---------------------------------------------------------------------------
// Init kernel: exact port of the reference Wigner-3j construction (fp64)
// ---------------------------------------------------------------------------
__device__ __forceinline__ double dfact(int n) {
  double r = 1.0;
  for (int i = 2; i <= n; ++i) r *= (double)i;
  return r;
}

__device__ double su2cg(int j1,int m1,int j2,int m2,int j3,int m3) {
  if (m1 + m2 != m3) return 0.0;
  int vmin = max(max(-j1+j2+m3, -j1+m1), 0);
  int vmax = min(min(j2+j3+m1, j3-j1+j2), j3+m3);
  double C = sqrt((2.0*j3+1.0)*dfact(j3+j1-j2)*dfact(j3-j1+j2)*dfact(j1+j2-j3)
                  *dfact(j3+m3)*dfact(j3-m3)
                  /(dfact(j1+j2+j3+1)*dfact(j1-m1)*dfact(j1+m1)*dfact(j2-m2)*dfact(j2+m2)));
  double S = 0.0;
  for (int v = vmin; v <= vmax; ++v) {
    double s = ((v + j2 + m2) & 1) ? -1.0 : 1.0;
    S += s * dfact(j2+j3+m1-v)*dfact(j1-m1+v)
         /(dfact(v)*dfact(j3-j1+j2-v)*dfact(j3+m3-v)*dfact(v+j1-j2-m3));
  }
  return C * S;
}

// q_real_to_complex(l)[r][c], including the (-i)^l phase
__device__ __forceinline__ void qent(int l, int r, int c, double* qr, double* qi) {
  const double inv2 = 0.7071067811865476;
  double re = 0.0, im = 0.0;
  int m = r - l;
  if (m < 0) {
    if (c == l - m) re = inv2;      // col l+|m|: 1/sqrt(2)
    if (c == l + m) im = -inv2;     // col l-|m|: -i/sqrt(2)
  } else if (m == 0) {
    if (c == l) re = 1.0;
  } else {
    double s = (m & 1) ? -1.0 : 1.0;
    if (c == l + m) re = s * inv2;  // (-1)^m/sqrt(2)
    if (c == l - m) im = s * inv2;  // i(-1)^m/sqrt(2)
  }
  // multiply by (-i)^l
  if (l == 1) { double t0 = re; re = im; im = -t0; }
  else if (l == 2) { re = -re; im = -im; }
  *qr = re; *qi = im;
}

__global__ void init_cg_kernel() {
  int t  = blockIdx.x;
  int l1 = TL1[t], l2 = TL2[t], l3 = TL3[t];
  int d1 = 2*l1+1, d2 = 2*l2+1, d3 = 2*l3+1;
  int n  = d1*d2*d3;
  __shared__ double cgc[125];
  __shared__ double cre[125];
  __shared__ double snrm;
  int tid = threadIdx.x;

  for (int e = tid; e < n; e += blockDim.x) {
    int i  = e/(d2*d3);
    int k  = (e/d3)%d2;
    int nn = e%d3;
    cgc[e] = su2cg(l1, i-l1, l2, k-l2, l3, nn-l3);
  }
  __syncthreads();

  // Creal[j,l,m] = Re sum_{i,k,n} Q1[i,j] Q2[k,l] conj(Q3[n,m]) Cg[i,k,n]
  for (int e = tid; e < n; e += blockDim.x) {
    int j = e/(d2*d3);
    int l = (e/d3)%d2;
    int m = e%d3;
    double acc = 0.0;
    for (int i = 0; i < d1; ++i) {
      for (int k = 0; k < d2; ++k) {
        int nn = (i-l1) + (k-l2) + l3;   // m3 = m1+m2
        if (nn < 0 || nn >= d3) continue;
        double cv = cgc[(i*d2+k)*d3+nn];
        if (cv == 0.0) continue;
        double q1r,q1i,q2r,q2i,q3r,q3i;
        qent(l1, i,  j, &q1r, &q1i);
        if (q1r == 0.0 && q1i == 0.0) continue;
        qent(l2, k,  l, &q2r, &q2i);
        if (q2r == 0.0 && q2i == 0.0) continue;
        qent(l3, nn, m, &q3r, &q3i);
        double tr = q1r*q2r - q1i*q2i;
        double ti = q1r*q2i + q1i*q2r;
        acc += cv * (tr*q3r + ti*q3i);   // Re( (q1*q2) * conj(q3) )
      }
    }
    cre[e] = acc;
  }
  __syncthreads();

  if (tid == 0) {
    double s = 0.0;
    for (int e = 0; e < n; ++e) s += cre[e]*cre[e];
    snrm = 1.0 / sqrt(s);
  }
  __syncthreads();

  double scale = snrm * TALPHA[t];
  for (int e = tid; e < NE; e += blockDim.x) {
    if (ENT_T[e] != t) continue;
    int idx = ((int)ENT_I[e]*d2 + (int)ENT_J[e])*d3 + (int)ENT_K[e];
    cg_coef[e] = (float)(cre[idx] * scale);
  }
}

// ---------------------------------------------------------------------------
// Main kernel: one thread per (z, u). All operands register-resident with
// compile-time indices; coefficients via broadcast LDS.
// Component index convention (9 locals): 0 = l0; 1..3 = l1; 4..8 = l2.
// ---------------------------------------------------------------------------
__global__ __launch_bounds__(256)
void tp_kernel(const float* __restrict__ X1, const float* __restrict__ X2,
               const float* __restrict__ W, float* __restrict__ OUT, int Z)
{
  __shared__ float g[NE];
  if (threadIdx.x < NE) g[threadIdx.x] = cg_coef[threadIdx.x];
  __syncthreads();

  int z = blockIdx.x * 2 + (threadIdx.x >> 7);
  int u = threadIdx.x & 127;
  if (z >= Z) return;

  const float* x1r = X1 + (long long)z * 1152;
  const float* x2r = X2 + (long long)z * 9;
  float*       outr = OUT + (long long)z * 1152;

  // x1 components for this u
  float xx0 = x1r[u];
  float xx1 = x1r[128 + 3*u    ];
  float xx2 = x1r[128 + 3*u + 1];
  float xx3 = x1r[128 + 3*u + 2];
  float xx4 = x1r[512 + 5*u    ];
  float xx5 = x1r[512 + 5*u + 1];
  float xx6 = x1r[512 + 5*u + 2];
  float xx7 = x1r[512 + 5*u + 3];
  float xx8 = x1r[512 + 5*u + 4];

  // x2 components (broadcast within warp)
  float y0 = x2r[0], y1 = x2r[1], y2 = x2r[2], y3 = x2r[3], y4 = x2r[4];
  float y5 = x2r[5], y6 = x2r[6], y7 = x2r[7], y8 = x2r[8];

  // per-instruction weights for this u
  float wv0  = W[          u];
  float wv1  = W[ 128 +    u];
  float wv2  = W[ 256 +    u];
  float wv3  = W[ 384 +    u];
  float wv4  = W[ 512 +    u];
  float wv5  = W[ 640 +    u];
  float wv6  = W[ 768 +    u];
  float wv7  = W[ 896 +    u];
  float wv8  = W[1024 +    u];
  float wv9  = W[1152 +    u];
  float wv10 = W[1280 +    u];

  float o0=0.f,o1=0.f,o2=0.f,o3=0.f,o4=0.f,o5=0.f,o6=0.f,o7=0.f,o8=0.f;

#define ACC(e,t,i,j,k) o##k = fmaf(g[e]*xx##i, wv##t*y##j, o##k);

  // t0 (0e x 0e -> 0e)
  ACC(0,0, 0,0,0)
  // t1 (0e x 1o -> 1o)
  ACC(1,1, 0,1,1)  ACC(2,1, 0,2,2)  ACC(3,1, 0,3,3)
  // t2 (0e x 2e -> 2e)
  ACC(4,2, 0,4,4)  ACC(5,2, 0,5,5)  ACC(6,2, 0,6,6)  ACC(7,2, 0,7,7)  ACC(8,2, 0,8,8)
  // t3 (1o x 0e -> 1o)
  ACC(9,3, 1,0,1)  ACC(10,3, 2,0,2)  ACC(11,3, 3,0,3)
  // t4 (1o x 1o -> 0e)
  ACC(12,4, 1,1,0) ACC(13,4, 2,2,0)  ACC(14,4, 3,3,0)
  // t5 (1o x 1o -> 2e)
  ACC(15,5, 2,2,6) ACC(16,5, 2,3,7) ACC(17,5, 2,1,5) ACC(18,5, 3,2,7)
  ACC(19,5, 1,2,5) ACC(20,5, 3,3,6) ACC(21,5, 1,1,6) ACC(22,5, 3,3,8)
  ACC(23,5, 1,1,8) ACC(24,5, 3,1,4) ACC(25,5, 1,3,4)
  // t6 (1o x 2e -> 1o)
  ACC(26,6, 2,6,2) ACC(27,6, 2,7,3) ACC(28,6, 2,5,1) ACC(29,6, 3,6,3)
  ACC(30,6, 1,6,1) ACC(31,6, 3,7,2) ACC(32,6, 1,5,2) ACC(33,6, 3,8,3)
  ACC(34,6, 1,8,1) ACC(35,6, 3,4,1) ACC(36,6, 1,4,3)
  // t7 (2e x 0e -> 2e)
  ACC(37,7, 4,0,4) ACC(38,7, 5,0,5) ACC(39,7, 6,0,6) ACC(40,7, 7,0,7) ACC(41,7, 8,0,8)
  // t8 (2e x 1o -> 1o)
  ACC(42,8, 6,2,2) ACC(43,8, 6,3,3) ACC(44,8, 6,1,1) ACC(45,8, 7,2,3)
  ACC(46,8, 5,2,1) ACC(47,8, 7,3,2) ACC(48,8, 5,1,2) ACC(49,8, 8,3,3)
  ACC(50,8, 8,1,1) ACC(51,8, 4,3,1) ACC(52,8, 4,1,3)
  // t9 (2e x 2e -> 0e)
  ACC(53,9, 4,4,0) ACC(54,9, 5,5,0) ACC(55,9, 6,6,0) ACC(56,9, 7,7,0) ACC(57,9, 8,8,0)
  // t10 (2e x 2e -> 2e)
  ACC(58,10, 6,6,6) ACC(59,10, 6,7,7) ACC(60,10, 6,5,5) ACC(61,10, 7,6,7)
  ACC(62,10, 5,6,5) ACC(63,10, 6,8,8) ACC(64,10, 6,4,4) ACC(65,10, 8,6,8)
  ACC(66,10, 4,6,4) ACC(67,10, 7,7,6) ACC(68,10, 5,5,6) ACC(69,10, 7,7,8)
  ACC(70,10, 5,5,8) ACC(71,10, 7,5,4) ACC(72,10, 5,7,4) ACC(73,10, 7,8,7)
  ACC(74,10, 5,8,5) ACC(75,10, 7,4,5) ACC(76,10, 5,4,7) ACC(77,10, 8,7,7)
  ACC(78,10, 4,7,5) ACC(79,10, 8,5,5) ACC(80,10, 4,5,7) ACC(81,10, 8,8,6)
  ACC(82,10, 4,4,6)
#undef ACC

  outr[u] = o0;
  outr[128 + 3*u    ] = o1;
  outr[128 + 3*u + 1] = o2;
  outr[128 + 3*u + 2] = o3;
  outr[512 + 5*u    ] = o4;
  outr[512 + 5*u + 1] = o5;
  outr[512 + 5*u + 2] = o6;
  outr[512 + 5*u + 3] = o7;
  outr[512 + 5*u + 4] = o8;
}

// ---------------------------------------------------------------------------
extern "C" void kernel_launch(void* const* d_in, const int* in_sizes, int n_in,
                              void* d_out, int out_size)
{
  // identify inputs by size (defensive): weight has 11*128=1408 elements,
  // x1 is the largest, x2 the remaining one.
  const float* x1 = (const float*)d_in[0];
  const float* x2 = (const float*)d_in[1];
  const float* w  = (const float*)d_in[2];
  if (n_in >= 3) {
    int iw = -1, imax = -1;
    long long smax = -1;
    for (int i = 0; i < 3; ++i) {
      if (in_sizes[i] == 1408) iw = i;
      if ((long long)in_sizes[i] > smax) { smax = in_sizes[i]; imax = i; }
    }
    if (iw >= 0 && imax >= 0 && iw != imax) {
      int ix2 = 3 - iw - imax;
      x1 = (const float*)d_in[imax];
      x2 = (const float*)d_in[ix2];
      w  = (const float*)d_in[iw];
    }
  }

  int Z = in_sizes[0] > in_sizes[1]
            ? (in_sizes[0] > in_sizes[2] ? in_sizes[0] : in_sizes[2])
            : (in_sizes[1] > in_sizes[2] ? in_sizes[1] : in_sizes[2]);
  Z /= 1152;

  init_cg_kernel<<<NT, 128>>>();
  int grid = (Z + 1) / 2;
  tp_kernel<<<grid, 256>>>(x1, x2, w, (float*)d_out, Z);
}